// round 1
// baseline (speedup 1.0000x reference)
#include <cuda_runtime.h>
#include <cuda_bf16.h>

#define Bn   2048
#define CELLn 512
#define Kn   30
#define Ln   1024
#define Vn   80
#define BPB  8          // batch rows per block in kernel 1

// scratch: per-b number of onehot rows kernel2 must read (phi==0 beyond)
__device__ int g_rows[Bn];

__device__ __forceinline__ float dot4(float4 a, float4 b) {
    return a.x * b.x + a.y * b.y + a.z * b.z + a.w * b.w;
}

// ---------------------------------------------------------------------------
// Kernel 1: params = exp(x W^T + b); kappa = kappa_old + pre_kappa;
//           phi[b,l] = (L/text_len) * sum_k alpha_k exp(-beta_k (kappa_k - l)^2)
// Warp w of each block owns batch row b = blockIdx.x*BPB + w.
// ---------------------------------------------------------------------------
__global__ __launch_bounds__(256) void k1_params_phi(
    const float* __restrict__ x, const float* __restrict__ kappa_old,
    const float* __restrict__ text_lens, const float* __restrict__ W,
    const float* __restrict__ bias, float* __restrict__ out)
{
    __shared__ float4 s_x[BPB][CELLn / 4];   // 16 KB
    __shared__ float4 s_par[BPB][Kn];        // .x=alpha .y=beta .z=kappa

    const int tid  = threadIdx.x;
    const int warp = tid >> 5;
    const int lane = tid & 31;
    const int b0   = blockIdx.x * BPB;

    // cooperative load of 8 x-rows into smem (coalesced float4)
    {
        const float4* xg = (const float4*)(x + (size_t)b0 * CELLn);
        float4* sx = &s_x[0][0];
        for (int i = tid; i < BPB * CELLn / 4; i += 256) sx[i] = xg[i];
    }
    __syncthreads();

    const int b = b0 + warp;
    const float4* Wv = (const float4*)W;

    // 90 dot products, 6 at a time per warp (ILP over the shfl reduction)
    for (int j0 = 0; j0 < 3 * Kn; j0 += 6) {
        float s0 = 0.f, s1 = 0.f, s2 = 0.f, s3 = 0.f, s4 = 0.f, s5 = 0.f;
        #pragma unroll
        for (int c = 0; c < 4; c++) {
            const int off = lane + 32 * c;
            float4 xv = s_x[warp][off];
            const float4* wp = Wv + (size_t)j0 * (CELLn / 4) + off;
            float4 w0 = wp[0 * (CELLn / 4)];
            float4 w1 = wp[1 * (CELLn / 4)];
            float4 w2 = wp[2 * (CELLn / 4)];
            float4 w3 = wp[3 * (CELLn / 4)];
            float4 w4 = wp[4 * (CELLn / 4)];
            float4 w5 = wp[5 * (CELLn / 4)];
            s0 += dot4(xv, w0);
            s1 += dot4(xv, w1);
            s2 += dot4(xv, w2);
            s3 += dot4(xv, w3);
            s4 += dot4(xv, w4);
            s5 += dot4(xv, w5);
        }
        #pragma unroll
        for (int o = 16; o; o >>= 1) {
            s0 += __shfl_xor_sync(0xffffffffu, s0, o);
            s1 += __shfl_xor_sync(0xffffffffu, s1, o);
            s2 += __shfl_xor_sync(0xffffffffu, s2, o);
            s3 += __shfl_xor_sync(0xffffffffu, s3, o);
            s4 += __shfl_xor_sync(0xffffffffu, s4, o);
            s5 += __shfl_xor_sync(0xffffffffu, s5, o);
        }
        if (lane == 0) {
            float sv[6] = {s0, s1, s2, s3, s4, s5};
            #pragma unroll
            for (int t = 0; t < 6; t++) {
                const int j = j0 + t;
                const float p = __expf(sv[t] + bias[j]);
                if (j < Kn) {
                    s_par[warp][j].x = p;                       // alpha
                } else if (j < 2 * Kn) {
                    s_par[warp][j - Kn].y = p;                  // beta
                } else {
                    const int kk = j - 2 * Kn;
                    const float kap = kappa_old[(size_t)b * Kn + kk] + p;
                    s_par[warp][kk].z = kap;                    // kappa
                    out[(size_t)Bn * Vn + (size_t)b * Kn + kk] = kap;
                }
            }
        }
    }
    __syncwarp();

    // per-b window end: beyond this, exp underflows to exactly 0 in fp32
    float wend = 0.0f;
    if (lane < Kn) {
        float4 pp = s_par[warp][lane];
        wend = pp.z + sqrtf(110.0f / pp.y);
    }
    #pragma unroll
    for (int o = 16; o; o >>= 1)
        wend = fmaxf(wend, __shfl_xor_sync(0xffffffffu, wend, o));
    int lend = (int)ceilf(wend);
    if (lend > Ln) lend = Ln;
    if (lane == 0) {
        int rows = lend + 1;
        if (rows > Ln) rows = Ln;   // w uses only l < L
        g_rows[b] = rows;
    }

    const float scale = (float)Ln / text_lens[b];
    float* phi_out = out + (size_t)Bn * Vn + (size_t)Bn * Kn + (size_t)b * (Ln + 1);

    for (int l = lane; l <= Ln; l += 32) {
        float s = 0.0f;
        if (l <= lend) {
            const float lf = (float)l;
            for (int k = 0; k < Kn; k++) {
                float4 p = s_par[warp][k];
                float d = p.z - lf;
                float g = -p.y * d * d;
                if (g > -110.0f) s += p.x * __expf(g);
            }
        }
        phi_out[l] = s * scale;
    }
}

// ---------------------------------------------------------------------------
// Kernel 2: w[b,v] = sum_{l<rows} phi[b,l] * onehots[b,l,v]  (phi==0 beyond rows)
// One block per b. Fully coalesced float4 stream over onehots[b, 0:rows, :].
// gcd(1024,80)=16 -> per-thread v-residues cycle with period 5 -> acc[5][4].
// ---------------------------------------------------------------------------
__global__ __launch_bounds__(256) void k2_w(
    const float* __restrict__ onehots, const float* __restrict__ phi_base,
    float* __restrict__ out)
{
    __shared__ float s_phi[Ln];
    __shared__ float s_w[Vn];

    const int tid = threadIdx.x;
    const int b   = blockIdx.x;
    const int rows = g_rows[b];

    const float* phi = phi_base + (size_t)b * (Ln + 1);
    for (int i = tid; i < rows; i += 256) s_phi[i] = phi[i];
    if (tid < Vn) s_w[tid] = 0.0f;
    __syncthreads();

    const float4* M = (const float4*)(onehots + (size_t)b * Ln * Vn);
    const int n4 = rows * (Vn / 4);   // 20 float4 per row

    float acc[5][4] = {{0.f,0.f,0.f,0.f},{0.f,0.f,0.f,0.f},{0.f,0.f,0.f,0.f},
                       {0.f,0.f,0.f,0.f},{0.f,0.f,0.f,0.f}};

    for (int base = 0; base < n4; base += 5 * 256) {
        #pragma unroll
        for (int j = 0; j < 5; j++) {
            const int i = base + j * 256 + tid;
            if (i < n4) {
                float4 m = M[i];
                float p = s_phi[i / 20];
                acc[j][0] += p * m.x;
                acc[j][1] += p * m.y;
                acc[j][2] += p * m.z;
                acc[j][3] += p * m.w;
            }
        }
    }

    #pragma unroll
    for (int j = 0; j < 5; j++) {
        const int v = (4 * tid + 64 * j) % Vn;   // base v of this residue class
        atomicAdd(&s_w[v + 0], acc[j][0]);
        atomicAdd(&s_w[v + 1], acc[j][1]);
        atomicAdd(&s_w[v + 2], acc[j][2]);
        atomicAdd(&s_w[v + 3], acc[j][3]);
    }
    __syncthreads();
    if (tid < Vn) out[(size_t)b * Vn + tid] = s_w[tid];
}

// ---------------------------------------------------------------------------
extern "C" void kernel_launch(void* const* d_in, const int* in_sizes, int n_in,
                              void* d_out, int out_size)
{
    const float* x         = (const float*)d_in[0];   // [B, CELL]
    const float* kappa_old = (const float*)d_in[1];   // [B, K]
    const float* onehots   = (const float*)d_in[2];   // [B, L, V]
    const float* text_lens = (const float*)d_in[3];   // [B, 1]
    const float* W         = (const float*)d_in[4];   // [3K, CELL]
    const float* bias      = (const float*)d_in[5];   // [3K]
    float* out = (float*)d_out;   // [w | kappa | phi]

    k1_params_phi<<<Bn / BPB, 256>>>(x, kappa_old, text_lens, W, bias, out);

    const float* phi_base = out + (size_t)Bn * Vn + (size_t)Bn * Kn;
    k2_w<<<Bn, 256>>>(onehots, phi_base, out);
}

// round 2
// speedup vs baseline: 2.4889x; 2.4889x over previous
#include <cuda_runtime.h>
#include <cuda_bf16.h>

#define Bn    2048
#define CELLn 512
#define Kn    30
#define Ln    1024
#define Vn    80
#define NJ    96      // 3K=90 padded to 96
#define KB    4       // K split across blocks
#define KCHUNK 128    // K range per block (4*128 = 512)
#define KSUB  64      // K per smem stage

// partial GEMM sums: g_part[kb][b][j]
__device__ float g_part[KB][Bn][NJ];

// ---------------------------------------------------------------------------
// k1: partial GEMM  g_part[kb][b][j] = sum_{k in chunk kb} x[b][k] * W[j][k]
// grid 256 = 64 mb-blocks x 4 kb-splits, 256 threads.
// warp w owns 4 b-rows (b0 + 4w + u); lane owns j = 3*lane .. 3*lane+2.
// ---------------------------------------------------------------------------
__global__ __launch_bounds__(256) void k1_gemm(const float* __restrict__ x,
                                               const float* __restrict__ W)
{
    __shared__ float4 sW[96 * 17];   // row pitch 17 float4 (conflict-free: 3*17=51, 51*l mod 8 distinct)
    __shared__ float4 sX[32 * 16];

    const int tid  = threadIdx.x;
    const int lane = tid & 31;
    const int w    = tid >> 5;
    const int mb   = blockIdx.x & 63;
    const int kb   = blockIdx.x >> 6;
    const int b0   = mb * 32;
    const int k0   = kb * KCHUNK;

    float acc[4][3] = {};

    const float4* Wg = (const float4*)W;
    const float4* Xg = (const float4*)x;

    for (int ch = 0; ch < 2; ch++) {
        const int kc4 = (k0 + ch * KSUB) >> 2;   // float4 offset into K
        // cooperative stage: W rows 0..89 (16 float4 each), x rows b0..b0+31
        #pragma unroll
        for (int t = 0; t < 6; t++) {
            int i = tid + t * 256;
            int j = i >> 4, c = i & 15;
            if (j < 90) sW[j * 17 + c] = Wg[(size_t)j * (CELLn / 4) + kc4 + c];
        }
        #pragma unroll
        for (int t = 0; t < 2; t++) {
            int i = tid + t * 256;
            int bl = i >> 4, c = i & 15;
            sX[bl * 16 + c] = Xg[(size_t)(b0 + bl) * (CELLn / 4) + kc4 + c];
        }
        __syncthreads();

        #pragma unroll
        for (int kc = 0; kc < 16; kc++) {
            float4 w0 = sW[(3 * lane + 0) * 17 + kc];
            float4 w1 = sW[(3 * lane + 1) * 17 + kc];
            float4 w2 = sW[(3 * lane + 2) * 17 + kc];
            #pragma unroll
            for (int u = 0; u < 4; u++) {
                float4 xv = sX[(w * 4 + u) * 16 + kc];   // warp-broadcast
                acc[u][0] += xv.x * w0.x + xv.y * w0.y + xv.z * w0.z + xv.w * w0.w;
                acc[u][1] += xv.x * w1.x + xv.y * w1.y + xv.z * w1.z + xv.w * w1.w;
                acc[u][2] += xv.x * w2.x + xv.y * w2.y + xv.z * w2.z + xv.w * w2.w;
            }
        }
        __syncthreads();
    }

    #pragma unroll
    for (int u = 0; u < 4; u++) {
        const int b = b0 + w * 4 + u;
        #pragma unroll
        for (int c = 0; c < 3; c++)
            g_part[kb][b][3 * lane + c] = acc[u][c];
    }
}

// ---------------------------------------------------------------------------
// k2: finish params (sum partials, +bias, exp, +kappa_old), compute phi
// (windowed by fp32-exact exp underflow), write phi/kappa, then
// w[b, 4*lane..4*lane+3] = sum_r phi[r] * onehots[b][r][4*lane..] (lanes 0..19).
// Warp per b, 8 warps per block, 256 blocks.
// ---------------------------------------------------------------------------
__global__ __launch_bounds__(256) void k2_fused(
    const float* __restrict__ onehots, const float* __restrict__ kappa_old,
    const float* __restrict__ text_lens, const float* __restrict__ bias,
    float* __restrict__ out)
{
    __shared__ float  s_phi[8][Ln];       // 32 KB
    __shared__ float4 s_abk[8][30];       // alpha, beta, kappa

    const int tid  = threadIdx.x;
    const int lane = tid & 31;
    const int w    = tid >> 5;
    const int b    = blockIdx.x * 8 + w;

    float wend = 0.0f;
    if (lane < 30) {
        float sa = 0.f, sb = 0.f, sk = 0.f;
        #pragma unroll
        for (int kb = 0; kb < KB; kb++) {
            sa += g_part[kb][b][lane];
            sb += g_part[kb][b][30 + lane];
            sk += g_part[kb][b][60 + lane];
        }
        const float alpha = __expf(sa + bias[lane]);
        const float beta  = __expf(sb + bias[30 + lane]);
        const float kap   = kappa_old[b * Kn + lane] + __expf(sk + bias[60 + lane]);
        out[(size_t)Bn * Vn + (size_t)b * Kn + lane] = kap;
        s_abk[w][lane] = make_float4(alpha, beta, kap, 0.f);
        wend = kap + sqrtf(110.0f / beta);
    }
    #pragma unroll
    for (int o = 16; o; o >>= 1)
        wend = fmaxf(wend, __shfl_xor_sync(0xffffffffu, wend, o));
    const int lend = min((int)ceilf(wend), Ln);
    __syncwarp();

    const float scale = (float)Ln / text_lens[b];
    float* phi_out = out + (size_t)Bn * Vn + (size_t)Bn * Kn + (size_t)b * (Ln + 1);

    for (int l = lane; l <= Ln; l += 32) {
        float s = 0.0f;
        if (l <= lend) {
            const float lf = (float)l;
            #pragma unroll 6
            for (int k = 0; k < Kn; k++) {
                float4 p = s_abk[w][k];
                float d = p.z - lf;
                float g = -p.y * d * d;
                if (g > -110.0f) s += p.x * __expf(g);
            }
        }
        const float v = s * scale;
        phi_out[l] = v;
        if (l < Ln) s_phi[w][l] = v;
    }
    __syncwarp();

    if (lane < 20) {
        const float4* M4 = (const float4*)onehots + (size_t)b * (Ln * Vn / 4);
        const int rows = min(lend + 1, Ln);
        float4 acc = make_float4(0.f, 0.f, 0.f, 0.f);
        int r = 0;
        for (; r + 4 <= rows; r += 4) {
            float4 m0 = M4[(size_t)(r + 0) * 20 + lane];
            float4 m1 = M4[(size_t)(r + 1) * 20 + lane];
            float4 m2 = M4[(size_t)(r + 2) * 20 + lane];
            float4 m3 = M4[(size_t)(r + 3) * 20 + lane];
            float p0 = s_phi[w][r + 0];
            float p1 = s_phi[w][r + 1];
            float p2 = s_phi[w][r + 2];
            float p3 = s_phi[w][r + 3];
            acc.x += p0 * m0.x; acc.y += p0 * m0.y; acc.z += p0 * m0.z; acc.w += p0 * m0.w;
            acc.x += p1 * m1.x; acc.y += p1 * m1.y; acc.z += p1 * m1.z; acc.w += p1 * m1.w;
            acc.x += p2 * m2.x; acc.y += p2 * m2.y; acc.z += p2 * m2.z; acc.w += p2 * m2.w;
            acc.x += p3 * m3.x; acc.y += p3 * m3.y; acc.z += p3 * m3.z; acc.w += p3 * m3.w;
        }
        for (; r < rows; r++) {
            float4 m = M4[(size_t)r * 20 + lane];
            float p = s_phi[w][r];
            acc.x += p * m.x; acc.y += p * m.y; acc.z += p * m.z; acc.w += p * m.w;
        }
        float4* wo = (float4*)(out + (size_t)b * Vn) + lane;
        *wo = acc;
    }
}

// ---------------------------------------------------------------------------
extern "C" void kernel_launch(void* const* d_in, const int* in_sizes, int n_in,
                              void* d_out, int out_size)
{
    const float* x         = (const float*)d_in[0];   // [B, CELL]
    const float* kappa_old = (const float*)d_in[1];   // [B, K]
    const float* onehots   = (const float*)d_in[2];   // [B, L, V]
    const float* text_lens = (const float*)d_in[3];   // [B, 1]
    const float* W         = (const float*)d_in[4];   // [3K, CELL]
    const float* bias      = (const float*)d_in[5];   // [3K]
    float* out = (float*)d_out;                       // [w | kappa | phi]

    k1_gemm<<<256, 256>>>(x, W);
    k2_fused<<<256, 256>>>(onehots, kappa_old, text_lens, bias, out);
}

// round 3
// speedup vs baseline: 2.8796x; 1.1570x over previous
#include <cuda_runtime.h>
#include <cuda_bf16.h>

#define Bn    2048
#define CELLn 512
#define Kn    30
#define Ln    1024
#define Vn    80
#define NJ    96      // 3K=90 padded to 96
#define KB    4       // K split across blocks in GEMM
#define KCHUNK 128
#define KSUB  64

// partial GEMM sums: g_part[kb][b][j]
__device__ float g_part[KB][Bn][NJ];

// ---------------------------------------------------------------------------
// k1: partial GEMM  g_part[kb][b][j] = sum_{k in chunk kb} x[b][k] * W[j][k]
// grid 256 = 64 mb-blocks x 4 kb-splits, 256 threads.
// ---------------------------------------------------------------------------
__global__ __launch_bounds__(256) void k1_gemm(const float* __restrict__ x,
                                               const float* __restrict__ W)
{
    __shared__ float4 sW[96 * 17];
    __shared__ float4 sX[32 * 16];

    const int tid  = threadIdx.x;
    const int lane = tid & 31;
    const int w    = tid >> 5;
    const int mb   = blockIdx.x & 63;
    const int kb   = blockIdx.x >> 6;
    const int b0   = mb * 32;
    const int k0   = kb * KCHUNK;

    float acc[4][3] = {};

    const float4* Wg = (const float4*)W;
    const float4* Xg = (const float4*)x;

    for (int ch = 0; ch < 2; ch++) {
        const int kc4 = (k0 + ch * KSUB) >> 2;
        #pragma unroll
        for (int t = 0; t < 6; t++) {
            int i = tid + t * 256;
            int j = i >> 4, c = i & 15;
            if (j < 90) sW[j * 17 + c] = Wg[(size_t)j * (CELLn / 4) + kc4 + c];
        }
        #pragma unroll
        for (int t = 0; t < 2; t++) {
            int i = tid + t * 256;
            int bl = i >> 4, c = i & 15;
            sX[bl * 16 + c] = Xg[(size_t)(b0 + bl) * (CELLn / 4) + kc4 + c];
        }
        __syncthreads();

        #pragma unroll
        for (int kc = 0; kc < 16; kc++) {
            float4 w0 = sW[(3 * lane + 0) * 17 + kc];
            float4 w1 = sW[(3 * lane + 1) * 17 + kc];
            float4 w2 = sW[(3 * lane + 2) * 17 + kc];
            #pragma unroll
            for (int u = 0; u < 4; u++) {
                float4 xv = sX[(w * 4 + u) * 16 + kc];
                acc[u][0] += xv.x * w0.x + xv.y * w0.y + xv.z * w0.z + xv.w * w0.w;
                acc[u][1] += xv.x * w1.x + xv.y * w1.y + xv.z * w1.z + xv.w * w1.w;
                acc[u][2] += xv.x * w2.x + xv.y * w2.y + xv.z * w2.z + xv.w * w2.w;
            }
        }
        __syncthreads();
    }

    #pragma unroll
    for (int u = 0; u < 4; u++) {
        const int b = b0 + w * 4 + u;
        #pragma unroll
        for (int c = 0; c < 3; c++)
            g_part[kb][b][3 * lane + c] = acc[u][c];
    }
}

// ---------------------------------------------------------------------------
// k2: block = 256 threads = 2 batch rows x 4 warps each.
// Per b-group: warp 0 finishes params (exp, +kappa_old) and computes window;
// 4 warps compute phi (128 threads strided over l); 4 warps split the onehots
// rows (r % 4), lanes 0..19 own fixed v-columns; smem reduce, warp 0 stores w.
// Grid = 1024 blocks -> 8192 warps (latency hiding for the DRAM stream).
// ---------------------------------------------------------------------------
__global__ __launch_bounds__(256) void k2_fused(
    const float* __restrict__ onehots, const float* __restrict__ kappa_old,
    const float* __restrict__ text_lens, const float* __restrict__ bias,
    float* __restrict__ out)
{
    __shared__ float  s_phi[2][Ln];        // 8 KB
    __shared__ float4 s_abk[2][30];        // alpha, beta, kappa
    __shared__ float4 s_red[2][4][20];     // per-warp partial w
    __shared__ int    s_lend[2];

    const int tid  = threadIdx.x;
    const int lane = tid & 31;
    const int g    = tid >> 7;            // b-group 0/1
    const int wg   = (tid >> 5) & 3;      // warp within group
    const int gt   = tid & 127;           // thread within group
    const int b    = blockIdx.x * 2 + g;

    // ---- params finish (one warp per group) ----
    if (wg == 0) {
        float wend = 0.0f;
        if (lane < 30) {
            float sa = 0.f, sb = 0.f, sk = 0.f;
            #pragma unroll
            for (int kb = 0; kb < KB; kb++) {
                sa += g_part[kb][b][lane];
                sb += g_part[kb][b][30 + lane];
                sk += g_part[kb][b][60 + lane];
            }
            const float alpha = __expf(sa + bias[lane]);
            const float beta  = __expf(sb + bias[30 + lane]);
            const float kap   = kappa_old[b * Kn + lane] + __expf(sk + bias[60 + lane]);
            out[(size_t)Bn * Vn + (size_t)b * Kn + lane] = kap;
            s_abk[g][lane] = make_float4(alpha, beta, kap, 0.f);
            wend = kap + sqrtf(110.0f / beta);
        }
        #pragma unroll
        for (int o = 16; o; o >>= 1)
            wend = fmaxf(wend, __shfl_xor_sync(0xffffffffu, wend, o));
        if (lane == 0) s_lend[g] = min((int)ceilf(wend), Ln);
    }
    __syncthreads();

    const int lend  = s_lend[g];
    const float scale = (float)Ln / text_lens[b];
    float* phi_out = out + (size_t)Bn * Vn + (size_t)Bn * Kn + (size_t)b * (Ln + 1);

    // ---- phi over 128 threads per b ----
    for (int l = gt; l <= Ln; l += 128) {
        float s = 0.0f;
        if (l <= lend) {
            const float lf = (float)l;
            #pragma unroll 6
            for (int k = 0; k < Kn; k++) {
                float4 p = s_abk[g][k];
                float d = p.z - lf;
                float gv = -p.y * d * d;
                if (gv > -110.0f) s += p.x * __expf(gv);
            }
        }
        const float v = s * scale;
        phi_out[l] = v;
        if (l < Ln) s_phi[g][l] = v;
    }
    __syncthreads();

    // ---- windowed contraction: 4 warps split rows, lanes 0..19 own v-cols ----
    const int rows = min(lend + 1, Ln);
    if (lane < 20) {
        const float4* M4 = (const float4*)onehots + (size_t)b * (Ln * Vn / 4);
        float4 acc = make_float4(0.f, 0.f, 0.f, 0.f);
        int r = wg;
        for (; r + 4 < rows; r += 8) {
            float4 m0 = M4[(size_t)r * 20 + lane];
            float4 m1 = M4[(size_t)(r + 4) * 20 + lane];
            float p0 = s_phi[g][r];
            float p1 = s_phi[g][r + 4];
            acc.x += p0 * m0.x; acc.y += p0 * m0.y; acc.z += p0 * m0.z; acc.w += p0 * m0.w;
            acc.x += p1 * m1.x; acc.y += p1 * m1.y; acc.z += p1 * m1.z; acc.w += p1 * m1.w;
        }
        for (; r < rows; r += 4) {
            float4 m = M4[(size_t)r * 20 + lane];
            float p = s_phi[g][r];
            acc.x += p * m.x; acc.y += p * m.y; acc.z += p * m.z; acc.w += p * m.w;
        }
        s_red[g][wg][lane] = acc;
    }
    __syncthreads();

    if (wg == 0 && lane < 20) {
        float4 a0 = s_red[g][0][lane];
        float4 a1 = s_red[g][1][lane];
        float4 a2 = s_red[g][2][lane];
        float4 a3 = s_red[g][3][lane];
        float4 s;
        s.x = (a0.x + a1.x) + (a2.x + a3.x);
        s.y = (a0.y + a1.y) + (a2.y + a3.y);
        s.z = (a0.z + a1.z) + (a2.z + a3.z);
        s.w = (a0.w + a1.w) + (a2.w + a3.w);
        ((float4*)(out + (size_t)b * Vn))[lane] = s;
    }
}

// ---------------------------------------------------------------------------
extern "C" void kernel_launch(void* const* d_in, const int* in_sizes, int n_in,
                              void* d_out, int out_size)
{
    const float* x         = (const float*)d_in[0];   // [B, CELL]
    const float* kappa_old = (const float*)d_in[1];   // [B, K]
    const float* onehots   = (const float*)d_in[2];   // [B, L, V]
    const float* text_lens = (const float*)d_in[3];   // [B, 1]
    const float* W         = (const float*)d_in[4];   // [3K, CELL]
    const float* bias      = (const float*)d_in[5];   // [3K]
    float* out = (float*)d_out;                       // [w | kappa | phi]

    k1_gemm<<<256, 256>>>(x, W);
    k2_fused<<<Bn / 2, 256>>>(onehots, kappa_old, text_lens, bias, out);
}

// round 4
// speedup vs baseline: 3.1248x; 1.0852x over previous
#include <cuda_runtime.h>
#include <cuda_bf16.h>

#define Bn    2048
#define CELLn 512
#define Kn    30
#define Ln    1024
#define Vn    80
#define NJ    96      // 3K=90 padded to 96
#define KB    4       // K split across blocks in GEMM
#define KCHUNK 128
#define KSUB  64

// partial GEMM sums: g_part[kb][b][j]
__device__ float g_part[KB][Bn][NJ];

// ---------------------------------------------------------------------------
// k1: partial GEMM  g_part[kb][b][j] = sum_{k in chunk kb} x[b][k] * W[j][k]
// grid 256 = 64 mb-blocks x 4 kb-splits, 256 threads.
// ---------------------------------------------------------------------------
__global__ __launch_bounds__(256) void k1_gemm(const float* __restrict__ x,
                                               const float* __restrict__ W)
{
    __shared__ float4 sW[96 * 17];
    __shared__ float4 sX[32 * 16];

    const int tid  = threadIdx.x;
    const int lane = tid & 31;
    const int w    = tid >> 5;
    const int mb   = blockIdx.x & 63;
    const int kb   = blockIdx.x >> 6;
    const int b0   = mb * 32;
    const int k0   = kb * KCHUNK;

    float acc[4][3] = {};

    const float4* Wg = (const float4*)W;
    const float4* Xg = (const float4*)x;

    for (int ch = 0; ch < 2; ch++) {
        const int kc4 = (k0 + ch * KSUB) >> 2;
        #pragma unroll
        for (int t = 0; t < 6; t++) {
            int i = tid + t * 256;
            int j = i >> 4, c = i & 15;
            if (j < 90) sW[j * 17 + c] = Wg[(size_t)j * (CELLn / 4) + kc4 + c];
        }
        #pragma unroll
        for (int t = 0; t < 2; t++) {
            int i = tid + t * 256;
            int bl = i >> 4, c = i & 15;
            sX[bl * 16 + c] = Xg[(size_t)(b0 + bl) * (CELLn / 4) + kc4 + c];
        }
        __syncthreads();

        #pragma unroll
        for (int kc = 0; kc < 16; kc++) {
            float4 w0 = sW[(3 * lane + 0) * 17 + kc];
            float4 w1 = sW[(3 * lane + 1) * 17 + kc];
            float4 w2 = sW[(3 * lane + 2) * 17 + kc];
            #pragma unroll
            for (int u = 0; u < 4; u++) {
                float4 xv = sX[(w * 4 + u) * 16 + kc];
                acc[u][0] += xv.x * w0.x + xv.y * w0.y + xv.z * w0.z + xv.w * w0.w;
                acc[u][1] += xv.x * w1.x + xv.y * w1.y + xv.z * w1.z + xv.w * w1.w;
                acc[u][2] += xv.x * w2.x + xv.y * w2.y + xv.z * w2.z + xv.w * w2.w;
            }
        }
        __syncthreads();
    }

    #pragma unroll
    for (int u = 0; u < 4; u++) {
        const int b = b0 + w * 4 + u;
        #pragma unroll
        for (int c = 0; c < 3; c++)
            g_part[kb][b][3 * lane + c] = acc[u][c];
    }
}

// ---------------------------------------------------------------------------
// k2: ONE block (128 threads, 4 warps) per batch row b.
// Phase A (overlapped): warps 1-3 + warp0 zero-fill phi row with STG.128
//                       while warp 0 also finishes params (exp, window).
// Phase B: windowed phi only for l <= lend (~1 strided iteration).
// Phase C: contraction, 4 warps split rows, lanes 0..19 own v-columns.
// ---------------------------------------------------------------------------
__global__ __launch_bounds__(128, 12) void k2_fused(
    const float* __restrict__ onehots, const float* __restrict__ kappa_old,
    const float* __restrict__ text_lens, const float* __restrict__ bias,
    float* __restrict__ out)
{
    __shared__ float  s_phi[Ln];        // 4 KB (windowed part only is used)
    __shared__ float4 s_abk[30];        // alpha, beta, kappa
    __shared__ float4 s_red[4][20];     // per-warp partial w
    __shared__ int    s_lend;

    const int tid  = threadIdx.x;
    const int lane = tid & 31;
    const int wg   = tid >> 5;
    const int b    = blockIdx.x;

    float* phi_out = out + (size_t)Bn * Vn + (size_t)Bn * Kn + (size_t)b * (Ln + 1);

    // ---- Phase A1: vectorized zero-fill of the phi row (all 128 threads) ----
    {
        const int mis = b & 3;                 // (base offset % 4) == b % 4
        const int l0  = (4 - mis) & 3;         // first 16B-aligned l
        const int n4  = (Ln + 1 - l0) >> 2;    // number of float4
        const int tail = Ln + 1 - l0 - (n4 << 2);
        if (tid < l0) phi_out[tid] = 0.0f;
        float4* p4 = (float4*)(phi_out + l0);
        const float4 z4 = make_float4(0.f, 0.f, 0.f, 0.f);
        for (int i = tid; i < n4; i += 128) p4[i] = z4;
        if (tid < tail) phi_out[l0 + (n4 << 2) + tid] = 0.0f;
    }

    // ---- Phase A2: params finish (warp 0) ----
    if (wg == 0) {
        float wend = 0.0f;
        if (lane < 30) {
            float sa = 0.f, sb = 0.f, sk = 0.f;
            #pragma unroll
            for (int kb = 0; kb < KB; kb++) {
                sa += g_part[kb][b][lane];
                sb += g_part[kb][b][30 + lane];
                sk += g_part[kb][b][60 + lane];
            }
            const float alpha = __expf(sa + bias[lane]);
            const float beta  = __expf(sb + bias[30 + lane]);
            const float kap   = kappa_old[b * Kn + lane] + __expf(sk + bias[60 + lane]);
            out[(size_t)Bn * Vn + (size_t)b * Kn + lane] = kap;
            s_abk[lane] = make_float4(alpha, beta, kap, 0.f);
            wend = kap + sqrtf(110.0f / beta);
        }
        #pragma unroll
        for (int o = 16; o; o >>= 1)
            wend = fmaxf(wend, __shfl_xor_sync(0xffffffffu, wend, o));
        if (lane == 0) s_lend = min((int)ceilf(wend), Ln);
    }
    __syncthreads();

    const int lend = s_lend;
    const float scale = (float)Ln / text_lens[b];

    // ---- Phase B: windowed phi (only l <= lend; overwrites the zeros) ----
    for (int l = tid; l <= lend; l += 128) {
        const float lf = (float)l;
        float s = 0.0f;
        #pragma unroll 6
        for (int k = 0; k < Kn; k++) {
            float4 p = s_abk[k];
            float d = p.z - lf;
            float gv = -p.y * d * d;
            if (gv > -110.0f) s += p.x * __expf(gv);
        }
        const float v = s * scale;
        phi_out[l] = v;
        if (l < Ln) s_phi[l] = v;
    }
    __syncthreads();

    // ---- Phase C: windowed contraction ----
    const int rows = min(lend + 1, Ln);
    if (lane < 20) {
        const float4* M4 = (const float4*)onehots + (size_t)b * (Ln * Vn / 4);
        float4 acc = make_float4(0.f, 0.f, 0.f, 0.f);
        int r = wg;
        for (; r + 4 < rows; r += 8) {
            float4 m0 = __ldcs(&M4[(size_t)r * 20 + lane]);
            float4 m1 = __ldcs(&M4[(size_t)(r + 4) * 20 + lane]);
            float p0 = s_phi[r];
            float p1 = s_phi[r + 4];
            acc.x += p0 * m0.x; acc.y += p0 * m0.y; acc.z += p0 * m0.z; acc.w += p0 * m0.w;
            acc.x += p1 * m1.x; acc.y += p1 * m1.y; acc.z += p1 * m1.z; acc.w += p1 * m1.w;
        }
        for (; r < rows; r += 4) {
            float4 m = __ldcs(&M4[(size_t)r * 20 + lane]);
            float p = s_phi[r];
            acc.x += p * m.x; acc.y += p * m.y; acc.z += p * m.z; acc.w += p * m.w;
        }
        s_red[wg][lane] = acc;
    }
    __syncthreads();

    if (wg == 0 && lane < 20) {
        float4 a0 = s_red[0][lane];
        float4 a1 = s_red[1][lane];
        float4 a2 = s_red[2][lane];
        float4 a3 = s_red[3][lane];
        float4 s;
        s.x = (a0.x + a1.x) + (a2.x + a3.x);
        s.y = (a0.y + a1.y) + (a2.y + a3.y);
        s.z = (a0.z + a1.z) + (a2.z + a3.z);
        s.w = (a0.w + a1.w) + (a2.w + a3.w);
        ((float4*)(out + (size_t)b * Vn))[lane] = s;
    }
}

// ---------------------------------------------------------------------------
extern "C" void kernel_launch(void* const* d_in, const int* in_sizes, int n_in,
                              void* d_out, int out_size)
{
    const float* x         = (const float*)d_in[0];   // [B, CELL]
    const float* kappa_old = (const float*)d_in[1];   // [B, K]
    const float* onehots   = (const float*)d_in[2];   // [B, L, V]
    const float* text_lens = (const float*)d_in[3];   // [B, 1]
    const float* W         = (const float*)d_in[4];   // [3K, CELL]
    const float* bias      = (const float*)d_in[5];   // [3K]
    float* out = (float*)d_out;                       // [w | kappa | phi]

    k1_gemm<<<256, 256>>>(x, W);
    k2_fused<<<Bn, 128>>>(onehots, kappa_old, text_lens, bias, out);
}